// round 7
// baseline (speedup 1.0000x reference)
#include <cuda_runtime.h>
#include <cuda_bf16.h>

// ---------------- problem constants ----------------
#define MAXN 100000
#define MAXE 1600000

// ---------------- scratch (device globals; no allocations allowed) ----------
__device__ __align__(16) float g_h  [MAXN * 64];  // per-layer transformed features
__device__ __align__(16) float g_agg[MAXN * 64];  // scatter accumulator
__device__ __align__(16) float g_act[MAXN * 64];  // layer activations
__device__ float g_deg [MAXN];
__device__ float g_dinv[MAXN];
__device__ float g_norm[MAXE];

// ---------------- kernels ----------------
__global__ void init_deg_kernel(float* __restrict__ deg, int n) {
    int i = blockIdx.x * blockDim.x + threadIdx.x;
    if (i < n) deg[i] = 1.0f;                    // self-loop contributes 1
}

// edge_index is int32 (JAX x64 disabled downcasts int64 -> int32).
// Layout: ei[0:E] = src, ei[E:2E] = dst.
__global__ void deg_kernel(const int* __restrict__ ei,
                           float* __restrict__ deg, int E, int n) {
    int e = blockIdx.x * blockDim.x + threadIdx.x;
    if (e >= E) return;
    int d = ei[E + e];
    if ((unsigned)d < (unsigned)n) atomicAdd(&deg[d], 1.0f);
}

__global__ void dinv_kernel(const float* __restrict__ deg, float* __restrict__ dinv, int n) {
    int i = blockIdx.x * blockDim.x + threadIdx.x;
    if (i < n) dinv[i] = rsqrtf(deg[i]);          // deg >= 1 always (self loop)
}

__global__ void norm_kernel(const int* __restrict__ ei,
                            const float* __restrict__ dinv, float* __restrict__ norm,
                            int E, int n) {
    int e = blockIdx.x * blockDim.x + threadIdx.x;
    if (e >= E) return;
    int s = ei[e];
    int d = ei[E + e];
    float v = 0.0f;
    if ((unsigned)s < (unsigned)n && (unsigned)d < (unsigned)n)
        v = dinv[s] * dinv[d];
    norm[e] = v;
}

// Dense per-row GEMM: H = X @ W (in_f = 64, OUTF = 64 or 32). Also zeroes AGG.
template<int OUTF>
__global__ void gemm_kernel(const float* __restrict__ X, const float* __restrict__ W,
                            float* __restrict__ H, float* __restrict__ AGG, int n) {
    constexpr int RPB = 256 / OUTF;               // rows per block
    __shared__ float sW[64 * OUTF];
    __shared__ float sX[RPB * 64];
    for (int i = threadIdx.x; i < 64 * OUTF; i += 256) sW[i] = W[i];
    int row0 = blockIdx.x * RPB;
    for (int i = threadIdx.x; i < RPB * 64; i += 256) {
        int r = row0 + i / 64;
        sX[i] = (r < n) ? X[(size_t)r * 64 + (i % 64)] : 0.0f;
    }
    __syncthreads();
    int lr  = threadIdx.x / OUTF;
    int col = threadIdx.x % OUTF;
    int row = row0 + lr;
    if (row < n) {
        float acc = 0.0f;
        #pragma unroll
        for (int k = 0; k < 64; k++)
            acc += sX[lr * 64 + k] * sW[k * OUTF + col];
        H  [(size_t)row * OUTF + col] = acc;
        AGG[(size_t)row * OUTF + col] = 0.0f;
    }
}

// Edge scatter: AGG[dst] += norm_e * H[src].
// OUTF/4 lanes per edge; atomicAdd (unused return) compiles to REDG.ADD.F32.
template<int OUTF>
__global__ void scatter_kernel(const int* __restrict__ ei,
                               const float* __restrict__ norm, const float* __restrict__ H,
                               float* __restrict__ AGG, int E, int n) {
    constexpr int LPE = OUTF / 4;                 // lanes per edge
    int t = blockIdx.x * blockDim.x + threadIdx.x;
    int e = t / LPE;
    int c = t % LPE;
    if (e >= E) return;
    int   s = __ldg(&ei[e]);
    int   d = __ldg(&ei[E + e]);
    if ((unsigned)s >= (unsigned)n || (unsigned)d >= (unsigned)n) return;
    float w = __ldg(&norm[e]);
    float4 v = *(const float4*)(H + (size_t)s * OUTF + c * 4);
    float* a = AGG + (size_t)d * OUTF + c * 4;
    atomicAdd(a + 0, v.x * w);
    atomicAdd(a + 1, v.y * w);
    atomicAdd(a + 2, v.z * w);
    atomicAdd(a + 3, v.w * w);
}

// OUT = (relu)(AGG + dinv^2 * H + b)   (self-loop folded in here)
template<int OUTF, bool RELU>
__global__ void finalize_kernel(const float* __restrict__ AGG, const float* __restrict__ H,
                                const float* __restrict__ dinv, const float* __restrict__ bias,
                                float* __restrict__ OUT, int n) {
    constexpr int LPR = OUTF / 4;
    int t = blockIdx.x * blockDim.x + threadIdx.x;
    int row = t / LPR;
    int c   = t % LPR;
    if (row >= n) return;
    float di = dinv[row];
    float sl = di * di;
    float4 a = *(const float4*)(AGG + (size_t)row * OUTF + c * 4);
    float4 h = *(const float4*)(H   + (size_t)row * OUTF + c * 4);
    float4 b = *(const float4*)(bias + c * 4);
    float4 o;
    o.x = a.x + sl * h.x + b.x;
    o.y = a.y + sl * h.y + b.y;
    o.z = a.z + sl * h.z + b.z;
    o.w = a.w + sl * h.w + b.w;
    if (RELU) {
        o.x = fmaxf(o.x, 0.0f); o.y = fmaxf(o.y, 0.0f);
        o.z = fmaxf(o.z, 0.0f); o.w = fmaxf(o.w, 0.0f);
    }
    *(float4*)(OUT + (size_t)row * OUTF + c * 4) = o;
}

// ---------------- launch ----------------
extern "C" void kernel_launch(void* const* d_in, const int* in_sizes, int n_in,
                              void* d_out, int out_size) {
    const float* x  = (const float*)d_in[0];
    const int*   ei = (const int*)d_in[1];      // int32: [0:E]=src, [E:2E]=dst
    const float* W1 = (const float*)d_in[2];
    const float* b1 = (const float*)d_in[3];
    const float* W2 = (const float*)d_in[4];
    const float* b2 = (const float*)d_in[5];
    const float* W3 = (const float*)d_in[6];
    const float* b3 = (const float*)d_in[7];
    float* out = (float*)d_out;

    const int n = in_sizes[0] / 64;
    const int E = in_sizes[1] / 2;

    float *p_h, *p_agg, *p_act, *p_deg, *p_dinv, *p_norm;
    cudaGetSymbolAddress((void**)&p_h,    g_h);
    cudaGetSymbolAddress((void**)&p_agg,  g_agg);
    cudaGetSymbolAddress((void**)&p_act,  g_act);
    cudaGetSymbolAddress((void**)&p_deg,  g_deg);
    cudaGetSymbolAddress((void**)&p_dinv, g_dinv);
    cudaGetSymbolAddress((void**)&p_norm, g_norm);

    const int B = 256;
    int gb_n = (n + B - 1) / B;
    int gb_e = (E + B - 1) / B;

    // ---- preprocessing ----
    init_deg_kernel<<<gb_n, B>>>(p_deg, n);
    deg_kernel<<<gb_e, B>>>(ei, p_deg, E, n);
    dinv_kernel<<<gb_n, B>>>(p_deg, p_dinv, n);
    norm_kernel<<<gb_e, B>>>(ei, p_dinv, p_norm, E, n);

    // grid sizes
    int gb_gemm64 = (n + 3) / 4;          // 4 rows/block
    int gb_gemm32 = (n + 7) / 8;          // 8 rows/block
    int gb_sc64   = (int)(((long long)E * 16 + B - 1) / B);
    int gb_sc32   = (int)(((long long)E * 8  + B - 1) / B);
    int gb_fin64  = (int)(((long long)n * 16 + B - 1) / B);
    int gb_fin32  = (int)(((long long)n * 8  + B - 1) / B);

    // ---- layer 1: x -> g_act ----
    gemm_kernel<64><<<gb_gemm64, B>>>(x, W1, p_h, p_agg, n);
    scatter_kernel<64><<<gb_sc64, B>>>(ei, p_norm, p_h, p_agg, E, n);
    finalize_kernel<64, true><<<gb_fin64, B>>>(p_agg, p_h, p_dinv, b1, p_act, n);

    // ---- layer 2: g_act -> g_act ----
    gemm_kernel<64><<<gb_gemm64, B>>>(p_act, W2, p_h, p_agg, n);
    scatter_kernel<64><<<gb_sc64, B>>>(ei, p_norm, p_h, p_agg, E, n);
    finalize_kernel<64, true><<<gb_fin64, B>>>(p_agg, p_h, p_dinv, b2, p_act, n);

    // ---- layer 3: g_act -> out (no relu) ----
    gemm_kernel<32><<<gb_gemm32, B>>>(p_act, W3, p_h, p_agg, n);
    scatter_kernel<32><<<gb_sc32, B>>>(ei, p_norm, p_h, p_agg, E, n);
    finalize_kernel<32, false><<<gb_fin32, B>>>(p_agg, p_h, p_dinv, b3, out, n);
}

// round 9
// speedup vs baseline: 3.1607x; 3.1607x over previous
#include <cuda_runtime.h>
#include <cuda_bf16.h>

// ---------------- problem constants ----------------
#define MAXN 100000
#define MAXE 1600000
#define SCAN_B 1024

// ---------------- scratch (device globals; no allocations allowed) ----------
__device__ __align__(16) float g_h   [MAXN * 64];   // transformed features (X@W)
__device__ __align__(16) float g_act [MAXN * 64];   // layer activations
__device__ float g_dinv  [MAXN];
__device__ int   g_cnt   [MAXN];
__device__ int   g_tmp   [MAXN];                    // per-block inclusive scan
__device__ int   g_bsum  [256];                     // block sums
__device__ int   g_rowptr[MAXN + 1];
__device__ int   g_esrc  [MAXE];                    // CSR-by-dst: src per slot
__device__ float g_ew    [MAXE];                    // CSR-by-dst: norm per slot

// ---------------- CSR build ----------------
__global__ void init_cnt_kernel(int* __restrict__ cnt, int n) {
    int i = blockIdx.x * blockDim.x + threadIdx.x;
    if (i < n) cnt[i] = 0;
}

// edge_index int32: ei[0:E]=src, ei[E:2E]=dst
__global__ void count_kernel(const int* __restrict__ ei, int* __restrict__ cnt,
                             int E, int n) {
    int e = blockIdx.x * blockDim.x + threadIdx.x;
    if (e >= E) return;
    int d = ei[E + e];
    if ((unsigned)d < (unsigned)n) atomicAdd(&cnt[d], 1);
}

__global__ void dinv_kernel(const int* __restrict__ cnt, float* __restrict__ dinv, int n) {
    int i = blockIdx.x * blockDim.x + threadIdx.x;
    if (i < n) dinv[i] = rsqrtf((float)cnt[i] + 1.0f);   // +1 self-loop
}

// inclusive scan within blocks of SCAN_B
__global__ void scan_block_kernel(const int* __restrict__ cnt, int* __restrict__ tmp,
                                  int* __restrict__ bsum, int n) {
    __shared__ int sh[SCAN_B];
    int i = blockIdx.x * SCAN_B + threadIdx.x;
    int v = (i < n) ? cnt[i] : 0;
    sh[threadIdx.x] = v;
    __syncthreads();
    for (int off = 1; off < SCAN_B; off <<= 1) {
        int t = (threadIdx.x >= off) ? sh[threadIdx.x - off] : 0;
        __syncthreads();
        sh[threadIdx.x] += t;
        __syncthreads();
    }
    if (i < n) tmp[i] = sh[threadIdx.x];
    if (threadIdx.x == SCAN_B - 1) bsum[blockIdx.x] = sh[SCAN_B - 1];
}

// exclusive scan of block sums (single block, nb <= 256)
__global__ void scan_bsum_kernel(int* __restrict__ bsum, int nb) {
    __shared__ int sh[256];
    int t = threadIdx.x;
    int v = (t < nb) ? bsum[t] : 0;
    sh[t] = v;
    __syncthreads();
    for (int off = 1; off < 256; off <<= 1) {
        int u = (t >= off) ? sh[t - off] : 0;
        __syncthreads();
        sh[t] += u;
        __syncthreads();
    }
    if (t < nb) bsum[t] = sh[t] - v;   // exclusive
}

__global__ void rowptr_kernel(const int* __restrict__ tmp, const int* __restrict__ bsum,
                              int* __restrict__ rowptr, int* __restrict__ cnt, int n) {
    int i = blockIdx.x * blockDim.x + threadIdx.x;
    if (i < n) {
        rowptr[i + 1] = tmp[i] + bsum[i / SCAN_B];
        cnt[i] = 0;                       // reuse as fill cursor
    }
    if (i == 0) rowptr[0] = 0;
}

__global__ void fill_csr_kernel(const int* __restrict__ ei, const float* __restrict__ dinv,
                                const int* __restrict__ rowptr, int* __restrict__ cnt,
                                int* __restrict__ esrc, float* __restrict__ ew,
                                int E, int n) {
    int e = blockIdx.x * blockDim.x + threadIdx.x;
    if (e >= E) return;
    int s = ei[e];
    int d = ei[E + e];
    if ((unsigned)s >= (unsigned)n || (unsigned)d >= (unsigned)n) return;
    int pos = rowptr[d] + atomicAdd(&cnt[d], 1);
    esrc[pos] = s;
    ew[pos]   = dinv[s] * dinv[d];
}

// ---------------- dense GEMM: H = X @ W (in_f=64) ----------------
template<int OUTF>
__global__ void gemm_kernel(const float* __restrict__ X, const float* __restrict__ W,
                            float* __restrict__ H, int n) {
    constexpr int RPB = 256 / OUTF;               // rows per block
    __shared__ float sW[64 * OUTF];
    __shared__ float sX[RPB * 64];
    for (int i = threadIdx.x; i < 64 * OUTF; i += 256) sW[i] = W[i];
    int row0 = blockIdx.x * RPB;
    for (int i = threadIdx.x; i < RPB * 64; i += 256) {
        int r = row0 + i / 64;
        sX[i] = (r < n) ? X[(size_t)r * 64 + (i % 64)] : 0.0f;
    }
    __syncthreads();
    int lr  = threadIdx.x / OUTF;
    int col = threadIdx.x % OUTF;
    int row = row0 + lr;
    if (row < n) {
        float acc = 0.0f;
        #pragma unroll
        for (int k = 0; k < 64; k++)
            acc += sX[lr * 64 + k] * sW[k * OUTF + col];
        H[(size_t)row * OUTF + col] = acc;
    }
}

// ---------------- fused gather-aggregate + finalize ----------------
// one warp per dst node; lanes tile the feature row; register accumulation;
// self-loop, bias, relu fused.  No atomics.
template<int OUTF, bool RELU>
__global__ void gather_kernel(const int* __restrict__ rowptr,
                              const int* __restrict__ esrc, const float* __restrict__ ew,
                              const float* __restrict__ H, const float* __restrict__ dinv,
                              const float* __restrict__ bias,
                              float* __restrict__ OUT, int n) {
    int warp = (blockIdx.x * blockDim.x + threadIdx.x) >> 5;
    int lane = threadIdx.x & 31;
    if (warp >= n) return;
    int node = warp;
    int beg = __ldg(&rowptr[node]);
    int end = __ldg(&rowptr[node + 1]);

    if (OUTF == 64) {
        int col = lane * 2;
        float ax = 0.0f, ay = 0.0f;
        int i = beg;
        for (; i + 1 < end; i += 2) {
            int   s0 = __ldg(&esrc[i]);
            int   s1 = __ldg(&esrc[i + 1]);
            float w0 = __ldg(&ew[i]);
            float w1 = __ldg(&ew[i + 1]);
            float2 v0 = *(const float2*)(H + (size_t)s0 * 64 + col);
            float2 v1 = *(const float2*)(H + (size_t)s1 * 64 + col);
            ax += w0 * v0.x + w1 * v1.x;
            ay += w0 * v0.y + w1 * v1.y;
        }
        if (i < end) {
            int   s0 = __ldg(&esrc[i]);
            float w0 = __ldg(&ew[i]);
            float2 v0 = *(const float2*)(H + (size_t)s0 * 64 + col);
            ax += w0 * v0.x;
            ay += w0 * v0.y;
        }
        float di = __ldg(&dinv[node]);
        float sl = di * di;
        float2 hh = *(const float2*)(H + (size_t)node * 64 + col);
        float2 bb = *(const float2*)(bias + col);
        float ox = ax + sl * hh.x + bb.x;
        float oy = ay + sl * hh.y + bb.y;
        if (RELU) { ox = fmaxf(ox, 0.0f); oy = fmaxf(oy, 0.0f); }
        *(float2*)(OUT + (size_t)node * 64 + col) = make_float2(ox, oy);
    } else { // OUTF == 32
        int col = lane;
        float a = 0.0f;
        int i = beg;
        for (; i + 1 < end; i += 2) {
            int   s0 = __ldg(&esrc[i]);
            int   s1 = __ldg(&esrc[i + 1]);
            float w0 = __ldg(&ew[i]);
            float w1 = __ldg(&ew[i + 1]);
            a += w0 * __ldg(H + (size_t)s0 * 32 + col)
               + w1 * __ldg(H + (size_t)s1 * 32 + col);
        }
        if (i < end) {
            a += __ldg(&ew[i]) * __ldg(H + (size_t)__ldg(&esrc[i]) * 32 + col);
        }
        float di = __ldg(&dinv[node]);
        float o = a + di * di * __ldg(H + (size_t)node * 32 + col) + __ldg(bias + col);
        if (RELU) o = fmaxf(o, 0.0f);
        OUT[(size_t)node * 32 + col] = o;
    }
}

// ---------------- launch ----------------
extern "C" void kernel_launch(void* const* d_in, const int* in_sizes, int n_in,
                              void* d_out, int out_size) {
    const float* x  = (const float*)d_in[0];
    const int*   ei = (const int*)d_in[1];      // int32: [0:E]=src, [E:2E]=dst
    const float* W1 = (const float*)d_in[2];
    const float* b1 = (const float*)d_in[3];
    const float* W2 = (const float*)d_in[4];
    const float* b2 = (const float*)d_in[5];
    const float* W3 = (const float*)d_in[6];
    const float* b3 = (const float*)d_in[7];
    float* out = (float*)d_out;

    const int n = in_sizes[0] / 64;
    const int E = in_sizes[1] / 2;

    float *p_h, *p_act, *p_dinv, *p_ew;
    int *p_cnt, *p_tmp, *p_bsum, *p_rowptr, *p_esrc;
    cudaGetSymbolAddress((void**)&p_h,      g_h);
    cudaGetSymbolAddress((void**)&p_act,    g_act);
    cudaGetSymbolAddress((void**)&p_dinv,   g_dinv);
    cudaGetSymbolAddress((void**)&p_cnt,    g_cnt);
    cudaGetSymbolAddress((void**)&p_tmp,    g_tmp);
    cudaGetSymbolAddress((void**)&p_bsum,   g_bsum);
    cudaGetSymbolAddress((void**)&p_rowptr, g_rowptr);
    cudaGetSymbolAddress((void**)&p_esrc,   g_esrc);
    cudaGetSymbolAddress((void**)&p_ew,     g_ew);

    const int B = 256;
    int gb_n  = (n + B - 1) / B;
    int gb_e  = (E + B - 1) / B;
    int nb    = (n + SCAN_B - 1) / SCAN_B;

    // ---- CSR build (amortized over 3 layers) ----
    init_cnt_kernel<<<gb_n, B>>>(p_cnt, n);
    count_kernel<<<gb_e, B>>>(ei, p_cnt, E, n);
    dinv_kernel<<<gb_n, B>>>(p_cnt, p_dinv, n);
    scan_block_kernel<<<nb, SCAN_B>>>(p_cnt, p_tmp, p_bsum, n);
    scan_bsum_kernel<<<1, 256>>>(p_bsum, nb);
    rowptr_kernel<<<gb_n, B>>>(p_tmp, p_bsum, p_rowptr, p_cnt, n);
    fill_csr_kernel<<<gb_e, B>>>(ei, p_dinv, p_rowptr, p_cnt, p_esrc, p_ew, E, n);

    int gb_gemm64  = (n + 3) / 4;              // 4 rows/block
    int gb_gemm32  = (n + 7) / 8;              // 8 rows/block
    int gb_gather  = (n * 32 + B - 1) / B;     // 1 warp per node, 8 warps/block

    // ---- layer 1: x -> g_act ----
    gemm_kernel<64><<<gb_gemm64, B>>>(x, W1, p_h, n);
    gather_kernel<64, true><<<gb_gather, B>>>(p_rowptr, p_esrc, p_ew, p_h, p_dinv, b1, p_act, n);

    // ---- layer 2: g_act -> g_act ----
    gemm_kernel<64><<<gb_gemm64, B>>>(p_act, W2, p_h, n);
    gather_kernel<64, true><<<gb_gather, B>>>(p_rowptr, p_esrc, p_ew, p_h, p_dinv, b2, p_act, n);

    // ---- layer 3: g_act -> out (no relu) ----
    gemm_kernel<32><<<gb_gemm32, B>>>(p_act, W3, p_h, n);
    gather_kernel<32, false><<<gb_gather, B>>>(p_rowptr, p_esrc, p_ew, p_h, p_dinv, b3, out, n);
}

// round 10
// speedup vs baseline: 4.0491x; 1.2811x over previous
#include <cuda_runtime.h>
#include <cuda_bf16.h>

// ---------------- problem constants ----------------
#define MAXN 100000
#define MAXE 1600000
#define SCAN_B 1024

// ---------------- scratch (device globals; no allocations allowed) ----------
__device__ __align__(16) float g_h   [MAXN * 64];   // transformed features (X@W)
__device__ __align__(16) float g_act [MAXN * 64];   // layer activations
__device__ float g_dinv  [MAXN];
__device__ int   g_cnt   [MAXN];
__device__ int   g_tmp   [MAXN];                    // per-block inclusive scan
__device__ int   g_bsum  [256];                     // block sums
__device__ int   g_rowptr[MAXN + 1];
__device__ __align__(16) int2 g_epack[MAXE];        // CSR-by-dst: (src, norm-bits)

// ---------------- CSR build ----------------
__global__ void init_cnt_kernel(int* __restrict__ cnt, int n) {
    int i = blockIdx.x * blockDim.x + threadIdx.x;
    if (i < n) cnt[i] = 0;
}

// edge_index int32: ei[0:E]=src, ei[E:2E]=dst
__global__ void count_kernel(const int* __restrict__ ei, int* __restrict__ cnt,
                             int E, int n) {
    int e = blockIdx.x * blockDim.x + threadIdx.x;
    if (e >= E) return;
    int d = ei[E + e];
    if ((unsigned)d < (unsigned)n) atomicAdd(&cnt[d], 1);
}

__global__ void dinv_kernel(const int* __restrict__ cnt, float* __restrict__ dinv, int n) {
    int i = blockIdx.x * blockDim.x + threadIdx.x;
    if (i < n) dinv[i] = rsqrtf((float)cnt[i] + 1.0f);   // +1 self-loop
}

// inclusive scan within blocks of SCAN_B
__global__ void scan_block_kernel(const int* __restrict__ cnt, int* __restrict__ tmp,
                                  int* __restrict__ bsum, int n) {
    __shared__ int sh[SCAN_B];
    int i = blockIdx.x * SCAN_B + threadIdx.x;
    int v = (i < n) ? cnt[i] : 0;
    sh[threadIdx.x] = v;
    __syncthreads();
    for (int off = 1; off < SCAN_B; off <<= 1) {
        int t = (threadIdx.x >= off) ? sh[threadIdx.x - off] : 0;
        __syncthreads();
        sh[threadIdx.x] += t;
        __syncthreads();
    }
    if (i < n) tmp[i] = sh[threadIdx.x];
    if (threadIdx.x == SCAN_B - 1) bsum[blockIdx.x] = sh[SCAN_B - 1];
}

// exclusive scan of block sums (single block, nb <= 256)
__global__ void scan_bsum_kernel(int* __restrict__ bsum, int nb) {
    __shared__ int sh[256];
    int t = threadIdx.x;
    int v = (t < nb) ? bsum[t] : 0;
    sh[t] = v;
    __syncthreads();
    for (int off = 1; off < 256; off <<= 1) {
        int u = (t >= off) ? sh[t - off] : 0;
        __syncthreads();
        sh[t] += u;
        __syncthreads();
    }
    if (t < nb) bsum[t] = sh[t] - v;   // exclusive
}

__global__ void rowptr_kernel(const int* __restrict__ tmp, const int* __restrict__ bsum,
                              int* __restrict__ rowptr, int* __restrict__ cnt, int n) {
    int i = blockIdx.x * blockDim.x + threadIdx.x;
    if (i < n) {
        rowptr[i + 1] = tmp[i] + bsum[i / SCAN_B];
        cnt[i] = 0;                       // reuse as fill cursor
    }
    if (i == 0) rowptr[0] = 0;
}

__global__ void fill_csr_kernel(const int* __restrict__ ei, const float* __restrict__ dinv,
                                const int* __restrict__ rowptr, int* __restrict__ cnt,
                                int2* __restrict__ epack, int E, int n) {
    int e = blockIdx.x * blockDim.x + threadIdx.x;
    if (e >= E) return;
    int s = ei[e];
    int d = ei[E + e];
    if ((unsigned)s >= (unsigned)n || (unsigned)d >= (unsigned)n) return;
    int pos = rowptr[d] + atomicAdd(&cnt[d], 1);
    epack[pos] = make_int2(s, __float_as_int(dinv[s] * dinv[d]));
}

// ---------------- dense GEMM: H = X @ W (in_f=64) ----------------
// Each thread computes a float4 of outputs: 1 broadcast LDS + 1 LDS.128 per 4 FMA.
template<int OUTF>
__global__ void gemm_kernel(const float* __restrict__ X, const float* __restrict__ W,
                            float* __restrict__ H, int n) {
    constexpr int TPR = OUTF / 4;                 // threads per row
    constexpr int RPB = 256 / TPR;                // rows per block
    __shared__ float4 sW[64 * TPR];               // W reinterpreted as float4 rows
    __shared__ float  sX[RPB * 64];
    for (int i = threadIdx.x; i < 64 * TPR; i += 256)
        sW[i] = ((const float4*)W)[i];
    int row0 = blockIdx.x * RPB;
    for (int i = threadIdx.x; i < RPB * 64; i += 256) {
        int r = row0 + (i >> 6);
        sX[i] = (r < n) ? X[(size_t)r * 64 + (i & 63)] : 0.0f;
    }
    __syncthreads();
    int lr = threadIdx.x / TPR;                   // local row
    int c4 = threadIdx.x % TPR;                   // float4 column group
    int row = row0 + lr;
    if (row < n) {
        float4 acc = make_float4(0.f, 0.f, 0.f, 0.f);
        #pragma unroll
        for (int k = 0; k < 64; k++) {
            float  xv = sX[lr * 64 + k];
            float4 wv = sW[k * TPR + c4];
            acc.x += xv * wv.x;
            acc.y += xv * wv.y;
            acc.z += xv * wv.z;
            acc.w += xv * wv.w;
        }
        ((float4*)(H + (size_t)row * OUTF))[c4] = acc;
    }
}

// ---------------- fused gather-aggregate + finalize ----------------
// one warp per dst node; lanes tile the feature row; 4-wide edge unroll for MLP;
// packed (src, norm) per edge; self-loop, bias, relu fused.  No atomics.
template<int OUTF, bool RELU>
__global__ void gather_kernel(const int* __restrict__ rowptr,
                              const int2* __restrict__ epack,
                              const float* __restrict__ H, const float* __restrict__ dinv,
                              const float* __restrict__ bias,
                              float* __restrict__ OUT, int n) {
    int warp = (blockIdx.x * blockDim.x + threadIdx.x) >> 5;
    int lane = threadIdx.x & 31;
    if (warp >= n) return;
    int node = warp;
    int beg = __ldg(&rowptr[node]);
    int end = __ldg(&rowptr[node + 1]);

    if (OUTF == 64) {
        int col = lane * 2;
        float ax = 0.0f, ay = 0.0f;
        int i = beg;
        for (; i + 3 < end; i += 4) {
            int2 e0 = __ldg(&epack[i]);
            int2 e1 = __ldg(&epack[i + 1]);
            int2 e2 = __ldg(&epack[i + 2]);
            int2 e3 = __ldg(&epack[i + 3]);
            float2 v0 = *(const float2*)(H + (size_t)e0.x * 64 + col);
            float2 v1 = *(const float2*)(H + (size_t)e1.x * 64 + col);
            float2 v2 = *(const float2*)(H + (size_t)e2.x * 64 + col);
            float2 v3 = *(const float2*)(H + (size_t)e3.x * 64 + col);
            float w0 = __int_as_float(e0.y), w1 = __int_as_float(e1.y);
            float w2 = __int_as_float(e2.y), w3 = __int_as_float(e3.y);
            ax += w0 * v0.x + w1 * v1.x + w2 * v2.x + w3 * v3.x;
            ay += w0 * v0.y + w1 * v1.y + w2 * v2.y + w3 * v3.y;
        }
        for (; i < end; i++) {
            int2 e0 = __ldg(&epack[i]);
            float2 v0 = *(const float2*)(H + (size_t)e0.x * 64 + col);
            float w0 = __int_as_float(e0.y);
            ax += w0 * v0.x;
            ay += w0 * v0.y;
        }
        float di = __ldg(&dinv[node]);
        float sl = di * di;
        float2 hh = *(const float2*)(H + (size_t)node * 64 + col);
        float2 bb = *(const float2*)(bias + col);
        float ox = ax + sl * hh.x + bb.x;
        float oy = ay + sl * hh.y + bb.y;
        if (RELU) { ox = fmaxf(ox, 0.0f); oy = fmaxf(oy, 0.0f); }
        *(float2*)(OUT + (size_t)node * 64 + col) = make_float2(ox, oy);
    } else { // OUTF == 32
        int col = lane;
        float a = 0.0f;
        int i = beg;
        for (; i + 3 < end; i += 4) {
            int2 e0 = __ldg(&epack[i]);
            int2 e1 = __ldg(&epack[i + 1]);
            int2 e2 = __ldg(&epack[i + 2]);
            int2 e3 = __ldg(&epack[i + 3]);
            float v0 = __ldg(H + (size_t)e0.x * 32 + col);
            float v1 = __ldg(H + (size_t)e1.x * 32 + col);
            float v2 = __ldg(H + (size_t)e2.x * 32 + col);
            float v3 = __ldg(H + (size_t)e3.x * 32 + col);
            a += __int_as_float(e0.y) * v0 + __int_as_float(e1.y) * v1
               + __int_as_float(e2.y) * v2 + __int_as_float(e3.y) * v3;
        }
        for (; i < end; i++) {
            int2 e0 = __ldg(&epack[i]);
            a += __int_as_float(e0.y) * __ldg(H + (size_t)e0.x * 32 + col);
        }
        float di = __ldg(&dinv[node]);
        float o = a + di * di * __ldg(H + (size_t)node * 32 + col) + __ldg(bias + col);
        if (RELU) o = fmaxf(o, 0.0f);
        OUT[(size_t)node * 32 + col] = o;
    }
}

// ---------------- launch ----------------
extern "C" void kernel_launch(void* const* d_in, const int* in_sizes, int n_in,
                              void* d_out, int out_size) {
    const float* x  = (const float*)d_in[0];
    const int*   ei = (const int*)d_in[1];      // int32: [0:E]=src, [E:2E]=dst
    const float* W1 = (const float*)d_in[2];
    const float* b1 = (const float*)d_in[3];
    const float* W2 = (const float*)d_in[4];
    const float* b2 = (const float*)d_in[5];
    const float* W3 = (const float*)d_in[6];
    const float* b3 = (const float*)d_in[7];
    float* out = (float*)d_out;

    const int n = in_sizes[0] / 64;
    const int E = in_sizes[1] / 2;

    float *p_h, *p_act, *p_dinv;
    int *p_cnt, *p_tmp, *p_bsum, *p_rowptr;
    int2 *p_epack;
    cudaGetSymbolAddress((void**)&p_h,      g_h);
    cudaGetSymbolAddress((void**)&p_act,    g_act);
    cudaGetSymbolAddress((void**)&p_dinv,   g_dinv);
    cudaGetSymbolAddress((void**)&p_cnt,    g_cnt);
    cudaGetSymbolAddress((void**)&p_tmp,    g_tmp);
    cudaGetSymbolAddress((void**)&p_bsum,   g_bsum);
    cudaGetSymbolAddress((void**)&p_rowptr, g_rowptr);
    cudaGetSymbolAddress((void**)&p_epack,  g_epack);

    const int B = 256;
    int gb_n  = (n + B - 1) / B;
    int gb_e  = (E + B - 1) / B;
    int nb    = (n + SCAN_B - 1) / SCAN_B;

    // ---- CSR build (amortized over 3 layers) ----
    init_cnt_kernel<<<gb_n, B>>>(p_cnt, n);
    count_kernel<<<gb_e, B>>>(ei, p_cnt, E, n);
    dinv_kernel<<<gb_n, B>>>(p_cnt, p_dinv, n);
    scan_block_kernel<<<nb, SCAN_B>>>(p_cnt, p_tmp, p_bsum, n);
    scan_bsum_kernel<<<1, 256>>>(p_bsum, nb);
    rowptr_kernel<<<gb_n, B>>>(p_tmp, p_bsum, p_rowptr, p_cnt, n);
    fill_csr_kernel<<<gb_e, B>>>(ei, p_dinv, p_rowptr, p_cnt, p_epack, E, n);

    int gb_gemm64 = (n + 15) / 16;             // 16 rows/block
    int gb_gemm32 = (n + 31) / 32;             // 32 rows/block
    int gb_gather = (n * 32 + B - 1) / B;      // 1 warp per node

    // ---- layer 1: x -> g_act ----
    gemm_kernel<64><<<gb_gemm64, B>>>(x, W1, p_h, n);
    gather_kernel<64, true><<<gb_gather, B>>>(p_rowptr, p_epack, p_h, p_dinv, b1, p_act, n);

    // ---- layer 2: g_act -> g_act ----
    gemm_kernel<64><<<gb_gemm64, B>>>(p_act, W2, p_h, n);
    gather_kernel<64, true><<<gb_gather, B>>>(p_rowptr, p_epack, p_h, p_dinv, b2, p_act, n);

    // ---- layer 3: g_act -> out (no relu) ----
    gemm_kernel<32><<<gb_gemm32, B>>>(p_act, W3, p_h, n);
    gather_kernel<32, false><<<gb_gather, B>>>(p_rowptr, p_epack, p_h, p_dinv, b3, out, n);
}

// round 11
// speedup vs baseline: 5.3081x; 1.3109x over previous
#include <cuda_runtime.h>
#include <cuda_bf16.h>

// ---------------- problem constants ----------------
#define MAXN 100000
#define MAXE 1600000
#define SCAN_B 1024

// ---------------- scratch (device globals; no allocations allowed) ----------
__device__ __align__(16) float g_h   [MAXN * 64];   // transformed features (X@W)
__device__ __align__(16) float g_act [MAXN * 64];   // layer activations
__device__ float g_dinv  [MAXN];
__device__ int   g_cnt   [MAXN];
__device__ int   g_tmp   [MAXN];                    // per-block inclusive scan
__device__ int   g_bsum  [256];                     // block sums
__device__ int   g_rowptr[MAXN + 1];
__device__ __align__(16) int2 g_epack[MAXE];        // CSR-by-dst: (src, norm-bits)

// ---------------- CSR build ----------------
__global__ void init_cnt_kernel(int* __restrict__ cnt, int n) {
    int i = blockIdx.x * blockDim.x + threadIdx.x;
    if (i < n) cnt[i] = 0;
}

// edge_index int32: ei[0:E]=src, ei[E:2E]=dst
__global__ void count_kernel(const int* __restrict__ ei, int* __restrict__ cnt,
                             int E, int n) {
    int e = blockIdx.x * blockDim.x + threadIdx.x;
    if (e >= E) return;
    int d = ei[E + e];
    if ((unsigned)d < (unsigned)n) atomicAdd(&cnt[d], 1);
}

__global__ void dinv_kernel(const int* __restrict__ cnt, float* __restrict__ dinv, int n) {
    int i = blockIdx.x * blockDim.x + threadIdx.x;
    if (i < n) dinv[i] = rsqrtf((float)cnt[i] + 1.0f);   // +1 self-loop
}

// inclusive scan within blocks of SCAN_B
__global__ void scan_block_kernel(const int* __restrict__ cnt, int* __restrict__ tmp,
                                  int* __restrict__ bsum, int n) {
    __shared__ int sh[SCAN_B];
    int i = blockIdx.x * SCAN_B + threadIdx.x;
    int v = (i < n) ? cnt[i] : 0;
    sh[threadIdx.x] = v;
    __syncthreads();
    for (int off = 1; off < SCAN_B; off <<= 1) {
        int t = (threadIdx.x >= off) ? sh[threadIdx.x - off] : 0;
        __syncthreads();
        sh[threadIdx.x] += t;
        __syncthreads();
    }
    if (i < n) tmp[i] = sh[threadIdx.x];
    if (threadIdx.x == SCAN_B - 1) bsum[blockIdx.x] = sh[SCAN_B - 1];
}

// exclusive scan of block sums (single block, nb <= 256)
__global__ void scan_bsum_kernel(int* __restrict__ bsum, int nb) {
    __shared__ int sh[256];
    int t = threadIdx.x;
    int v = (t < nb) ? bsum[t] : 0;
    sh[t] = v;
    __syncthreads();
    for (int off = 1; off < 256; off <<= 1) {
        int u = (t >= off) ? sh[t - off] : 0;
        __syncthreads();
        sh[t] += u;
        __syncthreads();
    }
    if (t < nb) bsum[t] = sh[t] - v;   // exclusive
}

__global__ void rowptr_kernel(const int* __restrict__ tmp, const int* __restrict__ bsum,
                              int* __restrict__ rowptr, int* __restrict__ cnt, int n) {
    int i = blockIdx.x * blockDim.x + threadIdx.x;
    if (i < n) {
        rowptr[i + 1] = tmp[i] + bsum[i / SCAN_B];
        cnt[i] = 0;                       // reuse as fill cursor
    }
    if (i == 0) rowptr[0] = 0;
}

__global__ void fill_csr_kernel(const int* __restrict__ ei, const float* __restrict__ dinv,
                                const int* __restrict__ rowptr, int* __restrict__ cnt,
                                int2* __restrict__ epack, int E, int n) {
    int e = blockIdx.x * blockDim.x + threadIdx.x;
    if (e >= E) return;
    int s = ei[e];
    int d = ei[E + e];
    if ((unsigned)s >= (unsigned)n || (unsigned)d >= (unsigned)n) return;
    int pos = rowptr[d] + atomicAdd(&cnt[d], 1);
    epack[pos] = make_int2(s, __float_as_int(dinv[s] * dinv[d]));
}

// ---------------- dense GEMM: H = X @ W (in_f=64) ----------------
// 4x4 register blocking: per k-step, 4 broadcast LDS + 1 LDS.128 feed 16 FFMA.
template<int OUTF>
__global__ void gemm_kernel(const float* __restrict__ X, const float* __restrict__ W,
                            float* __restrict__ H, int n) {
    constexpr int TPR = OUTF / 4;                 // thread-cols (float4 groups) per row
    constexpr int RPB = (256 / TPR) * 4;          // rows per block (4 rows/thread)
    __shared__ float4 sW[64 * TPR];
    __shared__ float  sX[RPB * 64];
    for (int i = threadIdx.x; i < 64 * TPR; i += 256)
        sW[i] = ((const float4*)W)[i];
    int row0 = blockIdx.x * RPB;
    for (int i = threadIdx.x; i < RPB * 16; i += 256) {   // float4 fills
        int r = row0 + (i >> 4);
        ((float4*)sX)[i] = (r < n) ? ((const float4*)(X + (size_t)r * 64))[i & 15]
                                   : make_float4(0.f, 0.f, 0.f, 0.f);
    }
    __syncthreads();
    int lr = (threadIdx.x / TPR) * 4;             // first of 4 local rows
    int c4 = threadIdx.x % TPR;                   // float4 column group
    float4 a0 = make_float4(0.f,0.f,0.f,0.f), a1 = a0, a2 = a0, a3 = a0;
    #pragma unroll
    for (int k = 0; k < 64; k++) {
        float4 wv = sW[k * TPR + c4];
        float x0 = sX[(lr + 0) * 64 + k];
        float x1 = sX[(lr + 1) * 64 + k];
        float x2 = sX[(lr + 2) * 64 + k];
        float x3 = sX[(lr + 3) * 64 + k];
        a0.x += x0*wv.x; a0.y += x0*wv.y; a0.z += x0*wv.z; a0.w += x0*wv.w;
        a1.x += x1*wv.x; a1.y += x1*wv.y; a1.z += x1*wv.z; a1.w += x1*wv.w;
        a2.x += x2*wv.x; a2.y += x2*wv.y; a2.z += x2*wv.z; a2.w += x2*wv.w;
        a3.x += x3*wv.x; a3.y += x3*wv.y; a3.z += x3*wv.z; a3.w += x3*wv.w;
    }
    int row = row0 + lr;
    if (row + 3 < n) {
        ((float4*)(H + (size_t)(row + 0) * OUTF))[c4] = a0;
        ((float4*)(H + (size_t)(row + 1) * OUTF))[c4] = a1;
        ((float4*)(H + (size_t)(row + 2) * OUTF))[c4] = a2;
        ((float4*)(H + (size_t)(row + 3) * OUTF))[c4] = a3;
    } else {
        if (row + 0 < n) ((float4*)(H + (size_t)(row + 0) * OUTF))[c4] = a0;
        if (row + 1 < n) ((float4*)(H + (size_t)(row + 1) * OUTF))[c4] = a1;
        if (row + 2 < n) ((float4*)(H + (size_t)(row + 2) * OUTF))[c4] = a2;
        if (row + 3 < n) ((float4*)(H + (size_t)(row + 3) * OUTF))[c4] = a3;
    }
}

// ---------------- fused gather-aggregate + finalize (64-wide) ----------------
// one warp per node; two half-warps process interleaved edges (stride 2, unroll 2);
// each half covers the 64-float row with 16 float4 lanes; xor-16 combine at end.
template<bool RELU>
__global__ void gather64_kernel(const int* __restrict__ rowptr,
                                const int2* __restrict__ epack,
                                const float* __restrict__ H, const float* __restrict__ dinv,
                                const float* __restrict__ bias,
                                float* __restrict__ OUT, int n) {
    int warp = (blockIdx.x * blockDim.x + threadIdx.x) >> 5;
    int lane = threadIdx.x & 31;
    if (warp >= n) return;
    int node = warp;
    int half = lane >> 4;
    int col  = (lane & 15) * 4;
    int beg = __ldg(&rowptr[node]);
    int end = __ldg(&rowptr[node + 1]);

    float4 acc = make_float4(0.f, 0.f, 0.f, 0.f);
    int i = beg + half;
    for (; i + 2 < end; i += 4) {
        int2 e0 = __ldg(&epack[i]);
        int2 e1 = __ldg(&epack[i + 2]);
        float4 v0 = *(const float4*)(H + (size_t)e0.x * 64 + col);
        float4 v1 = *(const float4*)(H + (size_t)e1.x * 64 + col);
        float w0 = __int_as_float(e0.y), w1 = __int_as_float(e1.y);
        acc.x += w0 * v0.x + w1 * v1.x;
        acc.y += w0 * v0.y + w1 * v1.y;
        acc.z += w0 * v0.z + w1 * v1.z;
        acc.w += w0 * v0.w + w1 * v1.w;
    }
    for (; i < end; i += 2) {
        int2 e0 = __ldg(&epack[i]);
        float4 v0 = *(const float4*)(H + (size_t)e0.x * 64 + col);
        float w0 = __int_as_float(e0.y);
        acc.x += w0 * v0.x; acc.y += w0 * v0.y;
        acc.z += w0 * v0.z; acc.w += w0 * v0.w;
    }
    // combine the two halves
    acc.x += __shfl_xor_sync(0xffffffffu, acc.x, 16);
    acc.y += __shfl_xor_sync(0xffffffffu, acc.y, 16);
    acc.z += __shfl_xor_sync(0xffffffffu, acc.z, 16);
    acc.w += __shfl_xor_sync(0xffffffffu, acc.w, 16);

    if (half == 0) {
        float di = __ldg(&dinv[node]);
        float sl = di * di;
        float4 hh = *(const float4*)(H + (size_t)node * 64 + col);
        float4 bb = *(const float4*)(bias + col);
        float4 o;
        o.x = acc.x + sl * hh.x + bb.x;
        o.y = acc.y + sl * hh.y + bb.y;
        o.z = acc.z + sl * hh.z + bb.z;
        o.w = acc.w + sl * hh.w + bb.w;
        if (RELU) {
            o.x = fmaxf(o.x, 0.f); o.y = fmaxf(o.y, 0.f);
            o.z = fmaxf(o.z, 0.f); o.w = fmaxf(o.w, 0.f);
        }
        *(float4*)(OUT + (size_t)node * 64 + col) = o;
    }
}

// ---------------- fused gather-aggregate + finalize (32-wide) ----------------
// one warp per node; four quarter-warps on interleaved edges (stride 4, unroll 2);
// each quarter covers the 32-float row with 8 float4 lanes; xor 8,16 combine.
template<bool RELU>
__global__ void gather32_kernel(const int* __restrict__ rowptr,
                                const int2* __restrict__ epack,
                                const float* __restrict__ H, const float* __restrict__ dinv,
                                const float* __restrict__ bias,
                                float* __restrict__ OUT, int n) {
    int warp = (blockIdx.x * blockDim.x + threadIdx.x) >> 5;
    int lane = threadIdx.x & 31;
    if (warp >= n) return;
    int node = warp;
    int grp = lane >> 3;
    int col = (lane & 7) * 4;
    int beg = __ldg(&rowptr[node]);
    int end = __ldg(&rowptr[node + 1]);

    float4 acc = make_float4(0.f, 0.f, 0.f, 0.f);
    int i = beg + grp;
    for (; i + 4 < end; i += 8) {
        int2 e0 = __ldg(&epack[i]);
        int2 e1 = __ldg(&epack[i + 4]);
        float4 v0 = *(const float4*)(H + (size_t)e0.x * 32 + col);
        float4 v1 = *(const float4*)(H + (size_t)e1.x * 32 + col);
        float w0 = __int_as_float(e0.y), w1 = __int_as_float(e1.y);
        acc.x += w0 * v0.x + w1 * v1.x;
        acc.y += w0 * v0.y + w1 * v1.y;
        acc.z += w0 * v0.z + w1 * v1.z;
        acc.w += w0 * v0.w + w1 * v1.w;
    }
    for (; i < end; i += 4) {
        int2 e0 = __ldg(&epack[i]);
        float4 v0 = *(const float4*)(H + (size_t)e0.x * 32 + col);
        float w0 = __int_as_float(e0.y);
        acc.x += w0 * v0.x; acc.y += w0 * v0.y;
        acc.z += w0 * v0.z; acc.w += w0 * v0.w;
    }
    #pragma unroll
    for (int off = 8; off <= 16; off <<= 1) {
        acc.x += __shfl_xor_sync(0xffffffffu, acc.x, off);
        acc.y += __shfl_xor_sync(0xffffffffu, acc.y, off);
        acc.z += __shfl_xor_sync(0xffffffffu, acc.z, off);
        acc.w += __shfl_xor_sync(0xffffffffu, acc.w, off);
    }
    if (lane < 8) {
        float di = __ldg(&dinv[node]);
        float sl = di * di;
        float4 hh = *(const float4*)(H + (size_t)node * 32 + col);
        float4 bb = *(const float4*)(bias + col);
        float4 o;
        o.x = acc.x + sl * hh.x + bb.x;
        o.y = acc.y + sl * hh.y + bb.y;
        o.z = acc.z + sl * hh.z + bb.z;
        o.w = acc.w + sl * hh.w + bb.w;
        if (RELU) {
            o.x = fmaxf(o.x, 0.f); o.y = fmaxf(o.y, 0.f);
            o.z = fmaxf(o.z, 0.f); o.w = fmaxf(o.w, 0.f);
        }
        *(float4*)(OUT + (size_t)node * 32 + col) = o;
    }
}

// ---------------- launch ----------------
extern "C" void kernel_launch(void* const* d_in, const int* in_sizes, int n_in,
                              void* d_out, int out_size) {
    const float* x  = (const float*)d_in[0];
    const int*   ei = (const int*)d_in[1];      // int32: [0:E]=src, [E:2E]=dst
    const float* W1 = (const float*)d_in[2];
    const float* b1 = (const float*)d_in[3];
    const float* W2 = (const float*)d_in[4];
    const float* b2 = (const float*)d_in[5];
    const float* W3 = (const float*)d_in[6];
    const float* b3 = (const float*)d_in[7];
    float* out = (float*)d_out;

    const int n = in_sizes[0] / 64;
    const int E = in_sizes[1] / 2;

    float *p_h, *p_act, *p_dinv;
    int *p_cnt, *p_tmp, *p_bsum, *p_rowptr;
    int2 *p_epack;
    cudaGetSymbolAddress((void**)&p_h,      g_h);
    cudaGetSymbolAddress((void**)&p_act,    g_act);
    cudaGetSymbolAddress((void**)&p_dinv,   g_dinv);
    cudaGetSymbolAddress((void**)&p_cnt,    g_cnt);
    cudaGetSymbolAddress((void**)&p_tmp,    g_tmp);
    cudaGetSymbolAddress((void**)&p_bsum,   g_bsum);
    cudaGetSymbolAddress((void**)&p_rowptr, g_rowptr);
    cudaGetSymbolAddress((void**)&p_epack,  g_epack);

    const int B = 256;
    int gb_n  = (n + B - 1) / B;
    int gb_e  = (E + B - 1) / B;
    int nb    = (n + SCAN_B - 1) / SCAN_B;

    // ---- CSR build (amortized over 3 layers) ----
    init_cnt_kernel<<<gb_n, B>>>(p_cnt, n);
    count_kernel<<<gb_e, B>>>(ei, p_cnt, E, n);
    dinv_kernel<<<gb_n, B>>>(p_cnt, p_dinv, n);
    scan_block_kernel<<<nb, SCAN_B>>>(p_cnt, p_tmp, p_bsum, n);
    scan_bsum_kernel<<<1, 256>>>(p_bsum, nb);
    rowptr_kernel<<<gb_n, B>>>(p_tmp, p_bsum, p_rowptr, p_cnt, n);
    fill_csr_kernel<<<gb_e, B>>>(ei, p_dinv, p_rowptr, p_cnt, p_epack, E, n);

    int gb_gemm64 = (n + 63) / 64;             // 64 rows/block
    int gb_gemm32 = (n + 127) / 128;           // 128 rows/block
    int gb_gather = (n * 32 + B - 1) / B;      // 1 warp per node

    // ---- layer 1: x -> g_act ----
    gemm_kernel<64><<<gb_gemm64, B>>>(x, W1, p_h, n);
    gather64_kernel<true><<<gb_gather, B>>>(p_rowptr, p_epack, p_h, p_dinv, b1, p_act, n);

    // ---- layer 2: g_act -> g_act ----
    gemm_kernel<64><<<gb_gemm64, B>>>(p_act, W2, p_h, n);
    gather64_kernel<true><<<gb_gather, B>>>(p_rowptr, p_epack, p_h, p_dinv, b2, p_act, n);

    // ---- layer 3: g_act -> out (no relu) ----
    gemm_kernel<32><<<gb_gemm32, B>>>(p_act, W3, p_h, n);
    gather32_kernel<false><<<gb_gather, B>>>(p_rowptr, p_epack, p_h, p_dinv, b3, out, n);
}

// round 13
// speedup vs baseline: 5.6728x; 1.0687x over previous
#include <cuda_runtime.h>
#include <cuda_bf16.h>

// ---------------- problem constants ----------------
#define MAXN 100000
#define MAXE 1600000
#define SCAN_B 1024

// ---------------- scratch (device globals; no allocations allowed) ----------
__device__ __align__(16) float g_h   [MAXN * 64];   // transformed features (X@W)
__device__ __align__(16) float g_act [MAXN * 64];   // layer activations
__device__ float g_dinv  [MAXN];
__device__ int   g_cnt   [MAXN];
__device__ int   g_tmp   [MAXN];                    // per-block inclusive scan
__device__ int   g_bsum  [256];                     // block sums
__device__ int   g_rowptr[MAXN + 1];
__device__ __align__(16) int2 g_epack[MAXE];        // CSR-by-dst: (src, norm-bits)

// ---------------- CSR build ----------------
__global__ void init_cnt_kernel(int* __restrict__ cnt, int n) {
    int i = blockIdx.x * blockDim.x + threadIdx.x;
    if (i < n) cnt[i] = 0;
}

// edge_index int32: ei[0:E]=src, ei[E:2E]=dst
__global__ void count_kernel(const int* __restrict__ ei, int* __restrict__ cnt,
                             int E, int n) {
    int e = blockIdx.x * blockDim.x + threadIdx.x;
    if (e >= E) return;
    int d = ei[E + e];
    if ((unsigned)d < (unsigned)n) atomicAdd(&cnt[d], 1);
}

__global__ void dinv_kernel(const int* __restrict__ cnt, float* __restrict__ dinv, int n) {
    int i = blockIdx.x * blockDim.x + threadIdx.x;
    if (i < n) dinv[i] = rsqrtf((float)cnt[i] + 1.0f);   // +1 self-loop
}

// inclusive scan within blocks of SCAN_B
__global__ void scan_block_kernel(const int* __restrict__ cnt, int* __restrict__ tmp,
                                  int* __restrict__ bsum, int n) {
    __shared__ int sh[SCAN_B];
    int i = blockIdx.x * SCAN_B + threadIdx.x;
    int v = (i < n) ? cnt[i] : 0;
    sh[threadIdx.x] = v;
    __syncthreads();
    for (int off = 1; off < SCAN_B; off <<= 1) {
        int t = (threadIdx.x >= off) ? sh[threadIdx.x - off] : 0;
        __syncthreads();
        sh[threadIdx.x] += t;
        __syncthreads();
    }
    if (i < n) tmp[i] = sh[threadIdx.x];
    if (threadIdx.x == SCAN_B - 1) bsum[blockIdx.x] = sh[SCAN_B - 1];
}

// exclusive scan of block sums (single block, nb <= 256)
__global__ void scan_bsum_kernel(int* __restrict__ bsum, int nb) {
    __shared__ int sh[256];
    int t = threadIdx.x;
    int v = (t < nb) ? bsum[t] : 0;
    sh[t] = v;
    __syncthreads();
    for (int off = 1; off < 256; off <<= 1) {
        int u = (t >= off) ? sh[t - off] : 0;
        __syncthreads();
        sh[t] += u;
        __syncthreads();
    }
    if (t < nb) bsum[t] = sh[t] - v;   // exclusive
}

__global__ void rowptr_kernel(const int* __restrict__ tmp, const int* __restrict__ bsum,
                              int* __restrict__ rowptr, int* __restrict__ cnt, int n) {
    int i = blockIdx.x * blockDim.x + threadIdx.x;
    if (i < n) {
        rowptr[i + 1] = tmp[i] + bsum[i / SCAN_B];
        cnt[i] = 0;                       // reuse as fill cursor
    }
    if (i == 0) rowptr[0] = 0;
}

__global__ void fill_csr_kernel(const int* __restrict__ ei, const float* __restrict__ dinv,
                                const int* __restrict__ rowptr, int* __restrict__ cnt,
                                int2* __restrict__ epack, int E, int n) {
    int e = blockIdx.x * blockDim.x + threadIdx.x;
    if (e >= E) return;
    int s = ei[e];
    int d = ei[E + e];
    if ((unsigned)s >= (unsigned)n || (unsigned)d >= (unsigned)n) return;
    int pos = rowptr[d] + atomicAdd(&cnt[d], 1);
    epack[pos] = make_int2(s, __float_as_int(dinv[s] * dinv[d]));
}

// ---------------- dense GEMM: H = X @ W (in_f=64) ----------------
// 4x4 register blocking: per k-step, 4 broadcast LDS + 1 LDS.128 feed 16 FFMA.
template<int OUTF>
__global__ void gemm_kernel(const float* __restrict__ X, const float* __restrict__ W,
                            float* __restrict__ H, int n) {
    constexpr int TPR = OUTF / 4;                 // thread-cols (float4 groups) per row
    constexpr int RPB = (256 / TPR) * 4;          // rows per block (4 rows/thread)
    __shared__ float4 sW[64 * TPR];
    __shared__ float  sX[RPB * 64];
    for (int i = threadIdx.x; i < 64 * TPR; i += 256)
        sW[i] = ((const float4*)W)[i];
    int row0 = blockIdx.x * RPB;
    for (int i = threadIdx.x; i < RPB * 16; i += 256) {   // float4 fills
        int r = row0 + (i >> 4);
        ((float4*)sX)[i] = (r < n) ? ((const float4*)(X + (size_t)r * 64))[i & 15]
                                   : make_float4(0.f, 0.f, 0.f, 0.f);
    }
    __syncthreads();
    int lr = (threadIdx.x / TPR) * 4;             // first of 4 local rows
    int c4 = threadIdx.x % TPR;                   // float4 column group
    float4 a0 = make_float4(0.f,0.f,0.f,0.f), a1 = a0, a2 = a0, a3 = a0;
    #pragma unroll
    for (int k = 0; k < 64; k++) {
        float4 wv = sW[k * TPR + c4];
        float x0 = sX[(lr + 0) * 64 + k];
        float x1 = sX[(lr + 1) * 64 + k];
        float x2 = sX[(lr + 2) * 64 + k];
        float x3 = sX[(lr + 3) * 64 + k];
        a0.x += x0*wv.x; a0.y += x0*wv.y; a0.z += x0*wv.z; a0.w += x0*wv.w;
        a1.x += x1*wv.x; a1.y += x1*wv.y; a1.z += x1*wv.z; a1.w += x1*wv.w;
        a2.x += x2*wv.x; a2.y += x2*wv.y; a2.z += x2*wv.z; a2.w += x2*wv.w;
        a3.x += x3*wv.x; a3.y += x3*wv.y; a3.z += x3*wv.z; a3.w += x3*wv.w;
    }
    int row = row0 + lr;
    if (row + 3 < n) {
        ((float4*)(H + (size_t)(row + 0) * OUTF))[c4] = a0;
        ((float4*)(H + (size_t)(row + 1) * OUTF))[c4] = a1;
        ((float4*)(H + (size_t)(row + 2) * OUTF))[c4] = a2;
        ((float4*)(H + (size_t)(row + 3) * OUTF))[c4] = a3;
    } else {
        if (row + 0 < n) ((float4*)(H + (size_t)(row + 0) * OUTF))[c4] = a0;
        if (row + 1 < n) ((float4*)(H + (size_t)(row + 1) * OUTF))[c4] = a1;
        if (row + 2 < n) ((float4*)(H + (size_t)(row + 2) * OUTF))[c4] = a2;
        if (row + 3 < n) ((float4*)(H + (size_t)(row + 3) * OUTF))[c4] = a3;
    }
}

// ---------------- fused gather-aggregate + finalize (64-wide) ----------------
// one warp per node; two half-warps process interleaved edges (stride 2, unroll 4:
// 8 edges in flight per warp); 16 float4 lanes cover the row; xor-16 combine.
template<bool RELU>
__global__ void gather64_kernel(const int* __restrict__ rowptr,
                                const int2* __restrict__ epack,
                                const float* __restrict__ H, const float* __restrict__ dinv,
                                const float* __restrict__ bias,
                                float* __restrict__ OUT, int n) {
    int warp = (blockIdx.x * blockDim.x + threadIdx.x) >> 5;
    int lane = threadIdx.x & 31;
    if (warp >= n) return;
    int node = warp;
    int half = lane >> 4;
    int col  = (lane & 15) * 4;
    int beg = __ldg(&rowptr[node]);
    int end = __ldg(&rowptr[node + 1]);

    float4 acc = make_float4(0.f, 0.f, 0.f, 0.f);
    int i = beg + half;
    for (; i + 6 < end; i += 8) {
        int2 e0 = __ldg(&epack[i]);
        int2 e1 = __ldg(&epack[i + 2]);
        int2 e2 = __ldg(&epack[i + 4]);
        int2 e3 = __ldg(&epack[i + 6]);
        float4 v0 = *(const float4*)(H + (size_t)e0.x * 64 + col);
        float4 v1 = *(const float4*)(H + (size_t)e1.x * 64 + col);
        float4 v2 = *(const float4*)(H + (size_t)e2.x * 64 + col);
        float4 v3 = *(const float4*)(H + (size_t)e3.x * 64 + col);
        float w0 = __int_as_float(e0.y), w1 = __int_as_float(e1.y);
        float w2 = __int_as_float(e2.y), w3 = __int_as_float(e3.y);
        acc.x += w0 * v0.x + w1 * v1.x + w2 * v2.x + w3 * v3.x;
        acc.y += w0 * v0.y + w1 * v1.y + w2 * v2.y + w3 * v3.y;
        acc.z += w0 * v0.z + w1 * v1.z + w2 * v2.z + w3 * v3.z;
        acc.w += w0 * v0.w + w1 * v1.w + w2 * v2.w + w3 * v3.w;
    }
    for (; i < end; i += 2) {
        int2 e0 = __ldg(&epack[i]);
        float4 v0 = *(const float4*)(H + (size_t)e0.x * 64 + col);
        float w0 = __int_as_float(e0.y);
        acc.x += w0 * v0.x; acc.y += w0 * v0.y;
        acc.z += w0 * v0.z; acc.w += w0 * v0.w;
    }
    // combine the two halves
    acc.x += __shfl_xor_sync(0xffffffffu, acc.x, 16);
    acc.y += __shfl_xor_sync(0xffffffffu, acc.y, 16);
    acc.z += __shfl_xor_sync(0xffffffffu, acc.z, 16);
    acc.w += __shfl_xor_sync(0xffffffffu, acc.w, 16);

    if (half == 0) {
        float di = __ldg(&dinv[node]);
        float sl = di * di;
        float4 hh = *(const float4*)(H + (size_t)node * 64 + col);
        float4 bb = *(const float4*)(bias + col);
        float4 o;
        o.x = acc.x + sl * hh.x + bb.x;
        o.y = acc.y + sl * hh.y + bb.y;
        o.z = acc.z + sl * hh.z + bb.z;
        o.w = acc.w + sl * hh.w + bb.w;
        if (RELU) {
            o.x = fmaxf(o.x, 0.f); o.y = fmaxf(o.y, 0.f);
            o.z = fmaxf(o.z, 0.f); o.w = fmaxf(o.w, 0.f);
        }
        *(float4*)(OUT + (size_t)node * 64 + col) = o;
    }
}

// ---------------- fused gather-aggregate + finalize (32-wide) ----------------
// one warp per node; four quarter-warps on interleaved edges (stride 4, unroll 4:
// 16 edges in flight per warp); 8 float4 lanes cover the row; xor 8,16 combine.
template<bool RELU>
__global__ void gather32_kernel(const int* __restrict__ rowptr,
                                const int2* __restrict__ epack,
                                const float* __restrict__ H, const float* __restrict__ dinv,
                                const float* __restrict__ bias,
                                float* __restrict__ OUT, int n) {
    int warp = (blockIdx.x * blockDim.x + threadIdx.x) >> 5;
    int lane = threadIdx.x & 31;
    if (warp >= n) return;
    int node = warp;
    int grp = lane >> 3;
    int col = (lane & 7) * 4;
    int beg = __ldg(&rowptr[node]);
    int end = __ldg(&rowptr[node + 1]);

    float4 acc = make_float4(0.f, 0.f, 0.f, 0.f);
    int i = beg + grp;
    for (; i + 12 < end; i += 16) {
        int2 e0 = __ldg(&epack[i]);
        int2 e1 = __ldg(&epack[i + 4]);
        int2 e2 = __ldg(&epack[i + 8]);
        int2 e3 = __ldg(&epack[i + 12]);
        float4 v0 = *(const float4*)(H + (size_t)e0.x * 32 + col);
        float4 v1 = *(const float4*)(H + (size_t)e1.x * 32 + col);
        float4 v2 = *(const float4*)(H + (size_t)e2.x * 32 + col);
        float4 v3 = *(const float4*)(H + (size_t)e3.x * 32 + col);
        float w0 = __int_as_float(e0.y), w1 = __int_as_float(e1.y);
        float w2 = __int_as_float(e2.y), w3 = __int_as_float(e3.y);
        acc.x += w0 * v0.x + w1 * v1.x + w2 * v2.x + w3 * v3.x;
        acc.y += w0 * v0.y + w1 * v1.y + w2 * v2.y + w3 * v3.y;
        acc.z += w0 * v0.z + w1 * v1.z + w2 * v2.z + w3 * v3.z;
        acc.w += w0 * v0.w + w1 * v1.w + w2 * v2.w + w3 * v3.w;
    }
    for (; i < end; i += 4) {
        int2 e0 = __ldg(&epack[i]);
        float4 v0 = *(const float4*)(H + (size_t)e0.x * 32 + col);
        float w0 = __int_as_float(e0.y);
        acc.x += w0 * v0.x; acc.y += w0 * v0.y;
        acc.z += w0 * v0.z; acc.w += w0 * v0.w;
    }
    #pragma unroll
    for (int off = 8; off <= 16; off <<= 1) {
        acc.x += __shfl_xor_sync(0xffffffffu, acc.x, off);
        acc.y += __shfl_xor_sync(0xffffffffu, acc.y, off);
        acc.z += __shfl_xor_sync(0xffffffffu, acc.z, off);
        acc.w += __shfl_xor_sync(0xffffffffu, acc.w, off);
    }
    if (lane < 8) {
        float di = __ldg(&dinv[node]);
        float sl = di * di;
        float4 hh = *(const float4*)(H + (size_t)node * 32 + col);
        float4 bb = *(const float4*)(bias + col);
        float4 o;
        o.x = acc.x + sl * hh.x + bb.x;
        o.y = acc.y + sl * hh.y + bb.y;
        o.z = acc.z + sl * hh.z + bb.z;
        o.w = acc.w + sl * hh.w + bb.w;
        if (RELU) {
            o.x = fmaxf(o.x, 0.f); o.y = fmaxf(o.y, 0.f);
            o.z = fmaxf(o.z, 0.f); o.w = fmaxf(o.w, 0.f);
        }
        *(float4*)(OUT + (size_t)node * 32 + col) = o;
    }
}

// ---------------- launch ----------------
extern "C" void kernel_launch(void* const* d_in, const int* in_sizes, int n_in,
                              void* d_out, int out_size) {
    const float* x  = (const float*)d_in[0];
    const int*   ei = (const int*)d_in[1];      // int32: [0:E]=src, [E:2E]=dst
    const float* W1 = (const float*)d_in[2];
    const float* b1 = (const float*)d_in[3];
    const float* W2 = (const float*)d_in[4];
    const float* b2 = (const float*)d_in[5];
    const float* W3 = (const float*)d_in[6];
    const float* b3 = (const float*)d_in[7];
    float* out = (float*)d_out;

    const int n = in_sizes[0] / 64;
    const int E = in_sizes[1] / 2;

    float *p_h, *p_act, *p_dinv;
    int *p_cnt, *p_tmp, *p_bsum, *p_rowptr;
    int2 *p_epack;
    cudaGetSymbolAddress((void**)&p_h,      g_h);
    cudaGetSymbolAddress((void**)&p_act,    g_act);
    cudaGetSymbolAddress((void**)&p_dinv,   g_dinv);
    cudaGetSymbolAddress((void**)&p_cnt,    g_cnt);
    cudaGetSymbolAddress((void**)&p_tmp,    g_tmp);
    cudaGetSymbolAddress((void**)&p_bsum,   g_bsum);
    cudaGetSymbolAddress((void**)&p_rowptr, g_rowptr);
    cudaGetSymbolAddress((void**)&p_epack,  g_epack);

    const int B = 256;
    int gb_n  = (n + B - 1) / B;
    int gb_e  = (E + B - 1) / B;
    int nb    = (n + SCAN_B - 1) / SCAN_B;

    // ---- CSR build (amortized over 3 layers) ----
    init_cnt_kernel<<<gb_n, B>>>(p_cnt, n);
    count_kernel<<<gb_e, B>>>(ei, p_cnt, E, n);
    dinv_kernel<<<gb_n, B>>>(p_cnt, p_dinv, n);
    scan_block_kernel<<<nb, SCAN_B>>>(p_cnt, p_tmp, p_bsum, n);
    scan_bsum_kernel<<<1, 256>>>(p_bsum, nb);
    rowptr_kernel<<<gb_n, B>>>(p_tmp, p_bsum, p_rowptr, p_cnt, n);
    fill_csr_kernel<<<gb_e, B>>>(ei, p_dinv, p_rowptr, p_cnt, p_epack, E, n);

    int gb_gemm64 = (n + 63) / 64;             // 64 rows/block
    int gb_gemm32 = (n + 127) / 128;           // 128 rows/block
    int gb_gather = (n * 32 + B - 1) / B;      // 1 warp per node

    // ---- layer 1: x -> g_act ----
    gemm_kernel<64><<<gb_gemm64, B>>>(x, W1, p_h, n);
    gather64_kernel<true><<<gb_gather, B>>>(p_rowptr, p_epack, p_h, p_dinv, b1, p_act, n);

    // ---- layer 2: g_act -> g_act ----
    gemm_kernel<64><<<gb_gemm64, B>>>(p_act, W2, p_h, n);
    gather64_kernel<true><<<gb_gather, B>>>(p_rowptr, p_epack, p_h, p_dinv, b2, p_act, n);

    // ---- layer 3: g_act -> out (no relu) ----
    gemm_kernel<32><<<gb_gemm32, B>>>(p_act, W3, p_h, n);
    gather32_kernel<false><<<gb_gather, B>>>(p_rowptr, p_epack, p_h, p_dinv, b3, out, n);
}